// round 12
// baseline (speedup 1.0000x reference)
#include <cuda_runtime.h>
#include <math.h>

#define LDIM 256
#define NPIX (LDIM * LDIM)      // 65536
#define TPB 256
#define HALF_F4 8192            // float4 per half-sample (128 rows x 64 f4)
#define ITERS (HALF_F4 / TPB)   // 32 float4 per thread

typedef unsigned long long u64;

// scratch (__device__ globals, zero-init: no allocation). B <= 8192.
__device__ float        g_ratios[8192];
__device__ float        g_pF[16384][3];   // per half: sumP, sumGP, sumG
__device__ int          g_pI[16384][4];   // per half: minR, maxR, minC, maxC
__device__ unsigned int g_tick[8192];     // per-sample ticket (combiner resets)
__device__ unsigned int g_ctr = 0;        // global ticket (self-resetting)

// ---- packed f32x2 helpers (sm_103a) ------------------------------------
__device__ __forceinline__ u64 pk2(float lo, float hi) {
    u64 r; asm("mov.b64 %0, {%1,%2};" : "=l"(r) : "f"(lo), "f"(hi)); return r;
}
__device__ __forceinline__ void upk2(u64 v, float &lo, float &hi) {
    asm("mov.b64 {%0,%1}, %2;" : "=f"(lo), "=f"(hi) : "l"(v));
}
__device__ __forceinline__ void add2(u64 &a, u64 b) {
    asm("add.rn.f32x2 %0, %1, %2;" : "=l"(a) : "l"(a), "l"(b));
}
__device__ __forceinline__ void fma2(u64 &a, u64 x, u64 y) {
    asm("fma.rn.f32x2 %0, %1, %2, %3;" : "=l"(a) : "l"(x), "l"(y), "l"(a));
}

__device__ __forceinline__ float wredsum(float v) {
#pragma unroll
    for (int o = 16; o; o >>= 1) v += __shfl_down_sync(0xffffffffu, v, o);
    return v;
}

// R4 retried with its actual defect fixed: __launch_bounds__(256,8) caps regs
// at 32 -> 8 CTAs/SM -> 1184 slots >= 1024 CTAs -> ONE wave (R4 had 44 regs ->
// 1.7 waves, which is what killed it). Finer CTA granularity cuts the per-SM
// load imbalance from 4-vs-3 samples (15.6% straggler excess) to 7-vs-6
// half-samples (1.2%). Two CTAs per sample (rows [0,128) / [128,256)); the
// SECOND arriver combines partials in fixed half0+half1 order, handles the
// gen-mask branch, writes the ratio; the LAST combiner overall does the
// fixed-order final sum + log. All tickets self-reset for graph replay; no
// spin-waits anywhere (arrive-and-proceed only), fully deterministic.
__global__ __launch_bounds__(TPB, 8) void sample_kernel(
    const float* __restrict__ Yp, const float* __restrict__ Yg,
    float* __restrict__ out, int B) {
    const int b = blockIdx.x >> 1;
    const int h = blockIdx.x & 1;
    const int t = threadIdx.x;
    const float4* P4 = reinterpret_cast<const float4*>(Yp + (size_t)b * NPIX) + h * HALF_F4;
    const float4* G4 = reinterpret_cast<const float4*>(Yg + (size_t)b * NPIX) + h * HALF_F4;

    u64 sP = 0ull, sGP = 0ull, sG = 0ull;     // packed {f32,f32} accumulators
    int minR = LDIM, maxR = -1, minC = LDIM, maxC = -1;
    const int c0 = (t & 63) * 4;              // this thread's fixed columns
    const int rb = h * 128 + (t >> 6);        // row = rb + 4*i

#pragma unroll 8
    for (int i = 0; i < ITERS; i++) {
        float4 p = P4[t + i * TPB];           // default caching (measured best)
        float4 g = G4[t + i * TPB];
        u64 p01 = pk2(p.x, p.y), p23 = pk2(p.z, p.w);
        u64 g01 = pk2(g.x, g.y), g23 = pk2(g.z, g.w);
        add2(sP, p01);  add2(sP, p23);            // sum Yp
        fma2(sGP, g01, p01); fma2(sGP, g23, p23); // sum Yg*Yp
        add2(sG, g01);  add2(sG, g23);            // sum Yg (>0 <=> max(Yg)>0)
        float m = fmaxf(fmaxf(p.x, p.y), fmaxf(p.z, p.w));
        if (m > 0.5f) {                        // rare: blob pixels only (~5%)
            int r = rb + 4 * i;
            minR = min(minR, r); maxR = max(maxR, r);
            if (p.x > 0.5f) { minC = min(minC, c0);     maxC = max(maxC, c0);     }
            if (p.y > 0.5f) { minC = min(minC, c0 + 1); maxC = max(maxC, c0 + 1); }
            if (p.z > 0.5f) { minC = min(minC, c0 + 2); maxC = max(maxC, c0 + 2); }
            if (p.w > 0.5f) { minC = min(minC, c0 + 3); maxC = max(maxC, c0 + 3); }
        }
    }

    float aP, bP, aGP, bGP, aG, bG;
    upk2(sP, aP, bP); upk2(sGP, aGP, bGP); upk2(sG, aG, bG);
    float fsP = aP + bP, fsGP = aGP + bGP, fsG = aG + bG;

    __shared__ float shF[3][8];
    __shared__ int   shI[4][8];
    __shared__ float bc[7];
    __shared__ int   shFlag;
    const int wid = t >> 5, lid = t & 31;

    fsP = wredsum(fsP); fsGP = wredsum(fsGP); fsG = wredsum(fsG);
    minR = __reduce_min_sync(0xffffffffu, minR);
    maxR = __reduce_max_sync(0xffffffffu, maxR);
    minC = __reduce_min_sync(0xffffffffu, minC);
    maxC = __reduce_max_sync(0xffffffffu, maxC);
    if (lid == 0) {
        shF[0][wid] = fsP; shF[1][wid] = fsGP; shF[2][wid] = fsG;
        shI[0][wid] = minR; shI[1][wid] = maxR; shI[2][wid] = minC; shI[3][wid] = maxC;
    }
    __syncthreads();
    if (t == 0) {
        float vP = 0.f, vGP = 0.f, vG = 0.f;
        int vminR = LDIM, vmaxR = -1, vminC = LDIM, vmaxC = -1;
#pragma unroll
        for (int w = 0; w < 8; w++) {
            vP += shF[0][w]; vGP += shF[1][w]; vG += shF[2][w];
            vminR = min(vminR, shI[0][w]); vmaxR = max(vmaxR, shI[1][w]);
            vminC = min(vminC, shI[2][w]); vmaxC = max(vmaxC, shI[3][w]);
        }
        const int hh = blockIdx.x;
        __stcg(&g_pF[hh][0], vP);  __stcg(&g_pF[hh][1], vGP); __stcg(&g_pF[hh][2], vG);
        g_pI[hh][0] = vminR; g_pI[hh][1] = vmaxR; g_pI[hh][2] = vminC; g_pI[hh][3] = vmaxC;
        __threadfence();                        // publish partials
        unsigned int old = atomicAdd(&g_tick[b], 1u);
        shFlag = (old == 1u) ? 1 : 0;           // second arriver combines
    }
    __syncthreads();

    if (shFlag) {
        // ---- combine halves (fixed order half0 + half1) ----
        if (t == 0) {
            g_tick[b] = 0;                      // reset for next graph replay
            __threadfence();                    // acquire partner partials
            const int h0 = 2 * b, h1 = 2 * b + 1;
            float vP  = __ldcg(&g_pF[h0][0]) + __ldcg(&g_pF[h1][0]);
            float vGP = __ldcg(&g_pF[h0][1]) + __ldcg(&g_pF[h1][1]);
            float vG  = __ldcg(&g_pF[h0][2]) + __ldcg(&g_pF[h1][2]);
            int vminR = min(__ldcg(&g_pI[h0][0]), __ldcg(&g_pI[h1][0]));
            int vmaxR = max(__ldcg(&g_pI[h0][1]), __ldcg(&g_pI[h1][1]));
            int vminC = min(__ldcg(&g_pI[h0][2]), __ldcg(&g_pI[h1][2]));
            int vmaxC = max(__ldcg(&g_pI[h0][3]), __ldcg(&g_pI[h1][3]));
            int left, right, up, down;
            if (vmaxR < 0) { left = 0; right = 0; up = 0; down = 0; } // argmax(all-False)=0
            else { left = vminR; right = (LDIM - 1) - vmaxR;
                   up = vminC;   down  = (LDIM - 1) - vmaxC; }
            int xr = (right - left) >> 1;       // == Python floor-div here
            int yr = (down - up) >> 1;
            bc[0] = vP;
            bc[1] = vGP;
            bc[2] = (vG > 0.f) ? 1.f : 0.f;
            bc[3] = (float)(left + xr);         // gt0 (vs column coord)
            bc[4] = (float)(up + yr);           // gt1 (vs row coord)
            bc[5] = (float)xr;
            bc[6] = (float)yr;
        }
        __syncthreads();

        const float sumP = bc[0], sumGP = bc[1];
        const bool hasGt = bc[2] > 0.5f;        // uniform across block

        if (!hasGt) {
            const float gt0 = bc[3], gt1 = bc[4], fxr = bc[5], fyr = bc[6];
            float acc = 0.f;
            if (fxr != 0.f && fyr != 0.f) {
                // mask support: exp(-h/(4/9)) > 0.1 <=> d0^4+d1^4 < 1.02337
                // => |d| <= 1.00579; pad bbox, test exactly per pixel.
                float radc = fabsf(fxr) * 1.01f + 1.0f;
                float radr = fabsf(fyr) * 1.01f + 1.0f;
                int cl = max(0, (int)floorf(gt0 - radc));
                int ch = min(LDIM - 1, (int)ceilf(gt0 + radc));
                int rl = max(0, (int)floorf(gt1 - radr));
                int rh = min(LDIM - 1, (int)ceilf(gt1 + radr));
                int W = ch - cl + 1;
                int tot = W * (rh - rl + 1);
                const float* Ps = Yp + (size_t)b * NPIX;
                for (int k = t; k < tot; k += TPB) {
                    int rr = rl + k / W;
                    int cc = cl + k % W;
                    float d0 = ((float)cc - gt0) / fxr;
                    float d1 = ((float)rr - gt1) / fyr;
                    float q0 = d0 * d0, q1 = d1 * d1;
                    float hh2 = q0 * q0 + q1 * q1;
                    if (expf(-hh2 / 0.44444445f) > 0.1f) acc += Ps[rr * LDIM + cc];
                }
            }
            acc = wredsum(acc);
            if (lid == 0) shF[0][wid] = acc;    // prior shF reads all complete
            __syncthreads();
            if (t == 0) {
                float pos = 0.f;
#pragma unroll
                for (int w = 0; w < 8; w++) pos += shF[0][w];
                __stcg(&g_ratios[b], (sumP - pos) / (pos + 1e-6f));
            }
        } else {
            if (t == 0) {
                __stcg(&g_ratios[b], (sumP - sumGP) / (sumGP + 1e-6f));
            }
        }
    }

    // ---- fused finalize: every CTA tickets; last of 2B does the final sum.
    // Ratio writers fenced their write before their ticket; the first-arriver
    // halves carry no ratio but their combiner partner always tickets after
    // them, so ticket==2B-1 implies all B ratios are published.
    if (t == 0) {
        __threadfence();
        unsigned int ticket = atomicAdd(&g_ctr, 1u);
        shFlag = (ticket == (unsigned int)(2 * B - 1)) ? 1 : 0;
    }
    __syncthreads();
    if (shFlag) {
        float v = 0.f;
        for (int i = t; i < B; i += TPB) v += __ldcg(&g_ratios[i]);
        v = wredsum(v);
        if (lid == 0) shF[1][wid] = v;
        __syncthreads();
        if (t == 0) {
            float total = 0.f;
#pragma unroll
            for (int w = 0; w < 8; w++) total += shF[1][w];
            out[0] = (total == 0.f) ? 0.f : (logf(total) / (float)B);
            g_ctr = 0;                          // reset for next graph replay
        }
    }
}

extern "C" void kernel_launch(void* const* d_in, const int* in_sizes, int n_in,
                              void* d_out, int out_size) {
    const float* Yp = (const float*)d_in[0];
    const float* Yg = (const float*)d_in[1];
    int B = in_sizes[0] / NPIX;   // 512
    sample_kernel<<<2 * B, TPB>>>(Yp, Yg, (float*)d_out, B);
}

// round 14
// speedup vs baseline: 1.1390x; 1.1390x over previous
#include <cuda_runtime.h>
#include <math.h>

#define LDIM 256
#define NPIX (LDIM * LDIM)     // 65536
#define TPB 512
#define ITERS (NPIX / 4 / TPB) // 32 float4 per thread

typedef unsigned long long u64;

// scratch (__device__ globals: no allocation). Sized for B <= 8192.
__device__ float        g_ratios[8192];
__device__ unsigned int g_ctr = 0;   // self-resetting ticket counter

// ---- packed f32x2 helpers (sm_103a) ------------------------------------
__device__ __forceinline__ u64 pk2(float lo, float hi) {
    u64 r; asm("mov.b64 %0, {%1,%2};" : "=l"(r) : "f"(lo), "f"(hi)); return r;
}
__device__ __forceinline__ void upk2(u64 v, float &lo, float &hi) {
    asm("mov.b64 {%0,%1}, %2;" : "=f"(lo), "=f"(hi) : "l"(v));
}
__device__ __forceinline__ void add2(u64 &a, u64 b) {
    asm("add.rn.f32x2 %0, %1, %2;" : "=l"(a) : "l"(a), "l"(b));
}
__device__ __forceinline__ void fma2(u64 &a, u64 x, u64 y) {
    asm("fma.rn.f32x2 %0, %1, %2, %3;" : "=l"(a) : "l"(x), "l"(y), "l"(a));
}

// ---- warp reductions ----------------------------------------------------
__device__ __forceinline__ float wredsum(float v) {
#pragma unroll
    for (int o = 16; o; o >>= 1) v += __shfl_down_sync(0xffffffffu, v, o);
    return v;
}

// FINAL CHAMPION (verified R9: 46.05us, R11: 46.53us kernel; DRAM ~74.5%).
// A/B-tested losers: .cs hint (+5us), .cg hint (+4.3us), 2-CTA split at
// occ 52% (+9us) AND at occ 89% (+9us -> split epilogue cost, not waves),
// work-stealing (+6.8us, epilogue serialization between items).
// Winning levers: single fused kernel (-4.3us vs separate finalize),
// __launch_bounds__(512,4) -> 32 regs -> whole 512-CTA grid resident in
// one wave (-7us). Deterministic: in-block fixed-order reductions only;
// last-block ticket does fixed-index final sum; ticket self-resets so every
// graph replay sees identical state.
__global__ __launch_bounds__(TPB, 4) void sample_kernel(
    const float* __restrict__ Yp, const float* __restrict__ Yg,
    float* __restrict__ out, int B) {
    const int b = blockIdx.x;
    const int t = threadIdx.x;
    const float4* P4 = reinterpret_cast<const float4*>(Yp + (size_t)b * NPIX);
    const float4* G4 = reinterpret_cast<const float4*>(Yg + (size_t)b * NPIX);

    u64 sP = 0ull, sGP = 0ull, sG = 0ull;     // packed {f32,f32} accumulators
    int minR = LDIM, maxR = -1, minC = LDIM, maxC = -1;
    const int c0 = (t & 63) * 4;              // this thread's fixed columns
    const int rb = t >> 6;                    // base row; row = rb + 8*i

#pragma unroll 8
    for (int i = 0; i < ITERS; i++) {
        float4 p = P4[t + i * TPB];           // default caching (measured best)
        float4 g = G4[t + i * TPB];
        u64 p01 = pk2(p.x, p.y), p23 = pk2(p.z, p.w);
        u64 g01 = pk2(g.x, g.y), g23 = pk2(g.z, g.w);
        add2(sP, p01);  add2(sP, p23);            // sum Yp
        fma2(sGP, g01, p01); fma2(sGP, g23, p23); // sum Yg*Yp
        add2(sG, g01);  add2(sG, g23);            // sum Yg (>0 <=> max(Yg)>0)
        float m = fmaxf(fmaxf(p.x, p.y), fmaxf(p.z, p.w));
        if (m > 0.5f) {                        // rare: blob pixels only (~5%)
            int r = rb + 8 * i;
            minR = min(minR, r); maxR = max(maxR, r);
            if (p.x > 0.5f) { minC = min(minC, c0);     maxC = max(maxC, c0);     }
            if (p.y > 0.5f) { minC = min(minC, c0 + 1); maxC = max(maxC, c0 + 1); }
            if (p.z > 0.5f) { minC = min(minC, c0 + 2); maxC = max(maxC, c0 + 2); }
            if (p.w > 0.5f) { minC = min(minC, c0 + 3); maxC = max(maxC, c0 + 3); }
        }
    }

    float aP, bP, aGP, bGP, aG, bG;
    upk2(sP, aP, bP); upk2(sGP, aGP, bGP); upk2(sG, aG, bG);
    float fsP = aP + bP, fsGP = aGP + bGP, fsG = aG + bG;

    __shared__ float shF[3][16];
    __shared__ int   shI[4][16];
    __shared__ float bc[7];
    __shared__ int   shLast;
    const int wid = t >> 5, lid = t & 31;

    fsP = wredsum(fsP); fsGP = wredsum(fsGP); fsG = wredsum(fsG);
    minR = __reduce_min_sync(0xffffffffu, minR);   // redux.sync: 1 instr each
    maxR = __reduce_max_sync(0xffffffffu, maxR);
    minC = __reduce_min_sync(0xffffffffu, minC);
    maxC = __reduce_max_sync(0xffffffffu, maxC);
    if (lid == 0) {
        shF[0][wid] = fsP; shF[1][wid] = fsGP; shF[2][wid] = fsG;
        shI[0][wid] = minR; shI[1][wid] = maxR; shI[2][wid] = minC; shI[3][wid] = maxC;
    }
    __syncthreads();
    if (wid == 0) {
        float vP  = (lid < 16) ? shF[0][lid] : 0.f;
        float vGP = (lid < 16) ? shF[1][lid] : 0.f;
        float vG  = (lid < 16) ? shF[2][lid] : 0.f;
        int vminR = (lid < 16) ? shI[0][lid] : LDIM;
        int vmaxR = (lid < 16) ? shI[1][lid] : -1;
        int vminC = (lid < 16) ? shI[2][lid] : LDIM;
        int vmaxC = (lid < 16) ? shI[3][lid] : -1;
        vP = wredsum(vP); vGP = wredsum(vGP); vG = wredsum(vG);
        vminR = __reduce_min_sync(0xffffffffu, vminR);
        vmaxR = __reduce_max_sync(0xffffffffu, vmaxR);
        vminC = __reduce_min_sync(0xffffffffu, vminC);
        vmaxC = __reduce_max_sync(0xffffffffu, vmaxC);
        if (lid == 0) {
            int left, right, up, down;
            if (vmaxR < 0) { left = 0; right = 0; up = 0; down = 0; } // argmax(all-False)=0
            else { left = vminR; right = (LDIM - 1) - vmaxR;
                   up = vminC;   down  = (LDIM - 1) - vmaxC; }
            int xr = (right - left) >> 1;   // arithmetic shift == Python floor-div
            int yr = (down - up) >> 1;
            bc[0] = vP;
            bc[1] = vGP;
            bc[2] = (vG > 0.f) ? 1.f : 0.f;
            bc[3] = (float)(left + xr);     // gt0 (vs column coord)
            bc[4] = (float)(up + yr);       // gt1 (vs row coord)
            bc[5] = (float)xr;
            bc[6] = (float)yr;
        }
    }
    __syncthreads();

    const float sumP = bc[0], sumGP = bc[1];
    const bool hasGt = bc[2] > 0.5f;   // uniform across block

    if (!hasGt) {
        const float gt0 = bc[3], gt1 = bc[4], fxr = bc[5], fyr = bc[6];
        float acc = 0.f;
        if (fxr != 0.f && fyr != 0.f) {
            // mask support: exp(-h/(4/9)) > 0.1  <=>  d0^4+d1^4 < 1.02337
            // => |d| <= 1.00579; pad bbox, test exactly per pixel.
            float radc = fabsf(fxr) * 1.01f + 1.0f;
            float radr = fabsf(fyr) * 1.01f + 1.0f;
            int cl = max(0, (int)floorf(gt0 - radc));
            int ch = min(LDIM - 1, (int)ceilf(gt0 + radc));
            int rl = max(0, (int)floorf(gt1 - radr));
            int rh = min(LDIM - 1, (int)ceilf(gt1 + radr));
            int W = ch - cl + 1;
            int tot = W * (rh - rl + 1);
            const float* Ps = Yp + (size_t)b * NPIX;
            for (int k = t; k < tot; k += TPB) {
                int rr = rl + k / W;
                int cc = cl + k % W;
                float d0 = ((float)cc - gt0) / fxr;
                float d1 = ((float)rr - gt1) / fyr;
                float q0 = d0 * d0, q1 = d1 * d1;
                float hh = q0 * q0 + q1 * q1;
                if (expf(-hh / 0.44444445f) > 0.1f) acc += Ps[rr * LDIM + cc];
            }
        }
        acc = wredsum(acc);
        if (lid == 0) shF[0][wid] = acc;   // everyone is past prior shF reads
        __syncthreads();
        if (t == 0) {
            float pos = 0.f;
#pragma unroll
            for (int w = 0; w < 16; w++) pos += shF[0][w];
            g_ratios[b] = (sumP - pos) / (pos + 1e-6f);
        }
    } else {
        if (t == 0) {
            g_ratios[b] = (sumP - sumGP) / (sumGP + 1e-6f);
        }
    }

    // ---- fused finalize: last block to arrive does the deterministic sum ----
    if (t == 0) {
        __threadfence();                       // publish g_ratios[b]
        unsigned int ticket = atomicAdd(&g_ctr, 1u);
        shLast = (ticket == (unsigned int)(B - 1)) ? 1 : 0;
    }
    __syncthreads();
    if (shLast) {
        // all B ratios published (every other block fenced before its ticket)
        float v = 0.f;
        for (int i = t; i < B; i += TPB) v += __ldcg(&g_ratios[i]);
        v = wredsum(v);
        if (lid == 0) shF[1][wid] = v;
        __syncthreads();
        if (t == 0) {
            float total = 0.f;
#pragma unroll
            for (int w = 0; w < 16; w++) total += shF[1][w];
            out[0] = (total == 0.f) ? 0.f : (logf(total) / (float)B);
            g_ctr = 0;                         // reset for next graph replay
        }
    }
}

extern "C" void kernel_launch(void* const* d_in, const int* in_sizes, int n_in,
                              void* d_out, int out_size) {
    const float* Yp = (const float*)d_in[0];
    const float* Yg = (const float*)d_in[1];
    int B = in_sizes[0] / NPIX;   // 512
    sample_kernel<<<B, TPB>>>(Yp, Yg, (float*)d_out, B);
}

// round 15
// speedup vs baseline: 1.1650x; 1.0229x over previous
#include <cuda_runtime.h>
#include <math.h>

#define LDIM 256
#define NPIX (LDIM * LDIM)     // 65536
#define TPB 512
#define ITERS (NPIX / 4 / TPB) // 32 float4 per thread

typedef unsigned long long u64;

// scratch (__device__ globals: no allocation). Sized for B <= 8192.
__device__ float        g_ratios[8192];
__device__ unsigned int g_ctr = 0;   // self-resetting ticket counter

// ---- packed f32x2 helpers (sm_103a) ------------------------------------
__device__ __forceinline__ u64 pk2(float lo, float hi) {
    u64 r; asm("mov.b64 %0, {%1,%2};" : "=l"(r) : "f"(lo), "f"(hi)); return r;
}
__device__ __forceinline__ void upk2(u64 v, float &lo, float &hi) {
    asm("mov.b64 {%0,%1}, %2;" : "=f"(lo), "=f"(hi) : "l"(v));
}
__device__ __forceinline__ void add2(u64 &a, u64 b) {
    asm("add.rn.f32x2 %0, %1, %2;" : "=l"(a) : "l"(a), "l"(b));
}
__device__ __forceinline__ void fma2(u64 &a, u64 x, u64 y) {
    asm("fma.rn.f32x2 %0, %1, %2, %3;" : "=l"(a) : "l"(x), "l"(y), "l"(a));
}

// ---- warp reductions ----------------------------------------------------
__device__ __forceinline__ float wredsum(float v) {
#pragma unroll
    for (int o = 16; o; o >>= 1) v += __shfl_down_sync(0xffffffffu, v, o);
    return v;
}

// FINAL CHAMPION — verified 3x (R9: 46.05us, R11: 46.53us, R14: 46.14us
// kernel; DRAM ~74.5-74.9%; rel_err 8.4e-8). A/B-tested losers: .cs hint
// (+5us), .cg hint (+4.3us), 2-CTA split at occ 52% (+9us) AND occ 89%
// (+9us -> split epilogue cost, not waves), work-stealing (+6.8us,
// inter-item serialization). Winning levers: single fused kernel (-4.3us
// vs separate finalize), __launch_bounds__(512,4) -> 32 regs -> whole
// 512-CTA grid resident in ONE wave (-7us). Deterministic: in-block
// fixed-order reductions only; last-block ticket does fixed-index final
// sum; ticket self-resets so every graph replay sees identical state.
__global__ __launch_bounds__(TPB, 4) void sample_kernel(
    const float* __restrict__ Yp, const float* __restrict__ Yg,
    float* __restrict__ out, int B) {
    const int b = blockIdx.x;
    const int t = threadIdx.x;
    const float4* P4 = reinterpret_cast<const float4*>(Yp + (size_t)b * NPIX);
    const float4* G4 = reinterpret_cast<const float4*>(Yg + (size_t)b * NPIX);

    u64 sP = 0ull, sGP = 0ull, sG = 0ull;     // packed {f32,f32} accumulators
    int minR = LDIM, maxR = -1, minC = LDIM, maxC = -1;
    const int c0 = (t & 63) * 4;              // this thread's fixed columns
    const int rb = t >> 6;                    // base row; row = rb + 8*i

#pragma unroll 8
    for (int i = 0; i < ITERS; i++) {
        float4 p = P4[t + i * TPB];           // default caching (measured best)
        float4 g = G4[t + i * TPB];
        u64 p01 = pk2(p.x, p.y), p23 = pk2(p.z, p.w);
        u64 g01 = pk2(g.x, g.y), g23 = pk2(g.z, g.w);
        add2(sP, p01);  add2(sP, p23);            // sum Yp
        fma2(sGP, g01, p01); fma2(sGP, g23, p23); // sum Yg*Yp
        add2(sG, g01);  add2(sG, g23);            // sum Yg (>0 <=> max(Yg)>0)
        float m = fmaxf(fmaxf(p.x, p.y), fmaxf(p.z, p.w));
        if (m > 0.5f) {                        // rare: blob pixels only (~5%)
            int r = rb + 8 * i;
            minR = min(minR, r); maxR = max(maxR, r);
            if (p.x > 0.5f) { minC = min(minC, c0);     maxC = max(maxC, c0);     }
            if (p.y > 0.5f) { minC = min(minC, c0 + 1); maxC = max(maxC, c0 + 1); }
            if (p.z > 0.5f) { minC = min(minC, c0 + 2); maxC = max(maxC, c0 + 2); }
            if (p.w > 0.5f) { minC = min(minC, c0 + 3); maxC = max(maxC, c0 + 3); }
        }
    }

    float aP, bP, aGP, bGP, aG, bG;
    upk2(sP, aP, bP); upk2(sGP, aGP, bGP); upk2(sG, aG, bG);
    float fsP = aP + bP, fsGP = aGP + bGP, fsG = aG + bG;

    __shared__ float shF[3][16];
    __shared__ int   shI[4][16];
    __shared__ float bc[7];
    __shared__ int   shLast;
    const int wid = t >> 5, lid = t & 31;

    fsP = wredsum(fsP); fsGP = wredsum(fsGP); fsG = wredsum(fsG);
    minR = __reduce_min_sync(0xffffffffu, minR);   // redux.sync: 1 instr each
    maxR = __reduce_max_sync(0xffffffffu, maxR);
    minC = __reduce_min_sync(0xffffffffu, minC);
    maxC = __reduce_max_sync(0xffffffffu, maxC);
    if (lid == 0) {
        shF[0][wid] = fsP; shF[1][wid] = fsGP; shF[2][wid] = fsG;
        shI[0][wid] = minR; shI[1][wid] = maxR; shI[2][wid] = minC; shI[3][wid] = maxC;
    }
    __syncthreads();
    if (wid == 0) {
        float vP  = (lid < 16) ? shF[0][lid] : 0.f;
        float vGP = (lid < 16) ? shF[1][lid] : 0.f;
        float vG  = (lid < 16) ? shF[2][lid] : 0.f;
        int vminR = (lid < 16) ? shI[0][lid] : LDIM;
        int vmaxR = (lid < 16) ? shI[1][lid] : -1;
        int vminC = (lid < 16) ? shI[2][lid] : LDIM;
        int vmaxC = (lid < 16) ? shI[3][lid] : -1;
        vP = wredsum(vP); vGP = wredsum(vGP); vG = wredsum(vG);
        vminR = __reduce_min_sync(0xffffffffu, vminR);
        vmaxR = __reduce_max_sync(0xffffffffu, vmaxR);
        vminC = __reduce_min_sync(0xffffffffu, vminC);
        vmaxC = __reduce_max_sync(0xffffffffu, vmaxC);
        if (lid == 0) {
            int left, right, up, down;
            if (vmaxR < 0) { left = 0; right = 0; up = 0; down = 0; } // argmax(all-False)=0
            else { left = vminR; right = (LDIM - 1) - vmaxR;
                   up = vminC;   down  = (LDIM - 1) - vmaxC; }
            int xr = (right - left) >> 1;   // arithmetic shift == Python floor-div
            int yr = (down - up) >> 1;
            bc[0] = vP;
            bc[1] = vGP;
            bc[2] = (vG > 0.f) ? 1.f : 0.f;
            bc[3] = (float)(left + xr);     // gt0 (vs column coord)
            bc[4] = (float)(up + yr);       // gt1 (vs row coord)
            bc[5] = (float)xr;
            bc[6] = (float)yr;
        }
    }
    __syncthreads();

    const float sumP = bc[0], sumGP = bc[1];
    const bool hasGt = bc[2] > 0.5f;   // uniform across block

    if (!hasGt) {
        const float gt0 = bc[3], gt1 = bc[4], fxr = bc[5], fyr = bc[6];
        float acc = 0.f;
        if (fxr != 0.f && fyr != 0.f) {
            // mask support: exp(-h/(4/9)) > 0.1  <=>  d0^4+d1^4 < 1.02337
            // => |d| <= 1.00579; pad bbox, test exactly per pixel.
            float radc = fabsf(fxr) * 1.01f + 1.0f;
            float radr = fabsf(fyr) * 1.01f + 1.0f;
            int cl = max(0, (int)floorf(gt0 - radc));
            int ch = min(LDIM - 1, (int)ceilf(gt0 + radc));
            int rl = max(0, (int)floorf(gt1 - radr));
            int rh = min(LDIM - 1, (int)ceilf(gt1 + radr));
            int W = ch - cl + 1;
            int tot = W * (rh - rl + 1);
            const float* Ps = Yp + (size_t)b * NPIX;
            for (int k = t; k < tot; k += TPB) {
                int rr = rl + k / W;
                int cc = cl + k % W;
                float d0 = ((float)cc - gt0) / fxr;
                float d1 = ((float)rr - gt1) / fyr;
                float q0 = d0 * d0, q1 = d1 * d1;
                float hh = q0 * q0 + q1 * q1;
                if (expf(-hh / 0.44444445f) > 0.1f) acc += Ps[rr * LDIM + cc];
            }
        }
        acc = wredsum(acc);
        if (lid == 0) shF[0][wid] = acc;   // everyone is past prior shF reads
        __syncthreads();
        if (t == 0) {
            float pos = 0.f;
#pragma unroll
            for (int w = 0; w < 16; w++) pos += shF[0][w];
            g_ratios[b] = (sumP - pos) / (pos + 1e-6f);
        }
    } else {
        if (t == 0) {
            g_ratios[b] = (sumP - sumGP) / (sumGP + 1e-6f);
        }
    }

    // ---- fused finalize: last block to arrive does the deterministic sum ----
    if (t == 0) {
        __threadfence();                       // publish g_ratios[b]
        unsigned int ticket = atomicAdd(&g_ctr, 1u);
        shLast = (ticket == (unsigned int)(B - 1)) ? 1 : 0;
    }
    __syncthreads();
    if (shLast) {
        // all B ratios published (every other block fenced before its ticket)
        float v = 0.f;
        for (int i = t; i < B; i += TPB) v += __ldcg(&g_ratios[i]);
        v = wredsum(v);
        if (lid == 0) shF[1][wid] = v;
        __syncthreads();
        if (t == 0) {
            float total = 0.f;
#pragma unroll
            for (int w = 0; w < 16; w++) total += shF[1][w];
            out[0] = (total == 0.f) ? 0.f : (logf(total) / (float)B);
            g_ctr = 0;                         // reset for next graph replay
        }
    }
}

extern "C" void kernel_launch(void* const* d_in, const int* in_sizes, int n_in,
                              void* d_out, int out_size) {
    const float* Yp = (const float*)d_in[0];
    const float* Yg = (const float*)d_in[1];
    int B = in_sizes[0] / NPIX;   // 512
    sample_kernel<<<B, TPB>>>(Yp, Yg, (float*)d_out, B);
}